// round 12
// baseline (speedup 1.0000x reference)
#include <cuda_runtime.h>
#include <math.h>

namespace cfg {
constexpr int B  = 32;
constexpr int S  = 512;
constexpr int E  = 512;
constexpr int T  = 24;
constexpr int H  = 2;
constexpr int HD = E / H;          // 256
constexpr int BS = B * S;          // 16384
}

// ---------------- scratch (static device globals; no allocation) ------------
__device__ float g_qkv[(size_t)cfg::B * cfg::S * 3 * cfg::E];
__device__ float g_scores[(size_t)cfg::B * cfg::H * cfg::S * cfg::S];
__device__ float g_attn[(size_t)cfg::B * cfg::S * cfg::E];
__device__ float g_dec [(size_t)cfg::B * cfg::S * cfg::E];
__device__ float g_em  [(size_t)cfg::B * cfg::S * cfg::T];
__device__ float g_num [cfg::B];
__device__ float g_den [cfg::B];
__device__ float g_msum[cfg::B];

// ---------------- helpers ----------------------------------------------------
__device__ __forceinline__ unsigned f2tf(unsigned rawf32) {
    unsigned u;
    asm("cvt.rna.tf32.f32 %0, %1;" : "=r"(u) : "f"(__uint_as_float(rawf32)));
    return u;
}

__device__ __forceinline__ void mma_tf32(float* d, const unsigned* a, const unsigned* b) {
    asm volatile(
        "mma.sync.aligned.m16n8k8.row.col.f32.tf32.tf32.f32 "
        "{%0,%1,%2,%3}, {%4,%5,%6,%7}, {%8,%9}, {%0,%1,%2,%3};"
        : "+f"(d[0]), "+f"(d[1]), "+f"(d[2]), "+f"(d[3])
        : "r"(a[0]), "r"(a[1]), "r"(a[2]), "r"(a[3]), "r"(b[0]), "r"(b[1]));
}

__device__ __forceinline__ void cp16(unsigned dst, const float* src, bool pred) {
    int sz = pred ? 16 : 0;
    asm volatile("cp.async.cg.shared.global [%0], [%1], 16, %2;"
                 :: "r"(dst), "l"(src), "r"(sz));
}
__device__ __forceinline__ void cp_commit() {
    asm volatile("cp.async.commit_group;");
}
template<int N0>
__device__ __forceinline__ void cp_wait() {
    asm volatile("cp.async.wait_group %0;" :: "n"(N0));
}

// ---------------- TF32 tensor-core GEMM, 3-stage cp.async pipeline ----------
// A: M x K (lda).  TRANSB: B is N x K (ldb) -> C=A*B^T.  else B is K x N (ldb).
// 128x128 tile, BK=16, 256 threads (8 warps, 2x4), warp tile 64x32,
// mma.sync.m16n8k8 tf32 with cvt.rna at fragment load.
// Dynamic SMEM: 3 stages x (As 2560 + Bs 2560) words = 61440 B.
template<bool TRANSB, bool RELU>
__global__ __launch_bounds__(256, 2)
void tgemm(const float* __restrict__ A, const float* __restrict__ Bp,
           float* __restrict__ C, const float* __restrict__ bias,
           int M, int N, int K, int lda, int ldb, int ldc, float alpha,
           int HH, int sab, int sah, int sbb, int sbh, int scb, int sch)
{
    constexpr int BK    = 16;
    constexpr int ASTR  = 20;
    constexpr int BSTRT = 20;
    constexpr int BSTRN = 136;
    constexpr int STGW  = 128 * ASTR;       // 2560 words per stage buffer
    constexpr unsigned STGB = STGW * 4;     // 10240 bytes

    int z = blockIdx.z;
    A  += (size_t)(z / HH) * sab + (size_t)(z % HH) * sah;
    Bp += (size_t)(z / HH) * sbb + (size_t)(z % HH) * sbh;
    C  += (size_t)(z / HH) * scb + (size_t)(z % HH) * sch;

    extern __shared__ unsigned sm[];
    unsigned* Asb = sm;                 // 3 * STGW
    unsigned* Bsb = sm + 3 * STGW;      // 3 * STGW

    const int tid  = threadIdx.x;
    const int warp = tid >> 5;
    const int lane = tid & 31;
    const int qid  = lane >> 2;
    const int cid  = lane & 3;

    const int m0 = blockIdx.y * 128;
    const int n0 = blockIdx.x * 128;
    const int wm = (warp >> 2) * 64;
    const int wn = (warp & 3) * 32;

    const int arow = tid >> 1;
    const int ak   = (tid & 1) * 8;
    const int bkk  = tid >> 4;
    const int bnn  = (tid & 15) * 8;

    float acc[4][4][4];
#pragma unroll
    for (int i = 0; i < 4; i++)
#pragma unroll
        for (int j = 0; j < 4; j++)
#pragma unroll
            for (int r = 0; r < 4; r++) acc[i][j][r] = 0.f;

    const int nt = K / BK;

    const unsigned as_b = (unsigned)__cvta_generic_to_shared(&Asb[arow * ASTR + ak]);
    const unsigned bs_b = TRANSB
        ? (unsigned)__cvta_generic_to_shared(&Bsb[arow * BSTRT + ak])
        : (unsigned)__cvta_generic_to_shared(&Bsb[bkk * BSTRN + bnn]);
    const bool bval = TRANSB ? (n0 + arow < N) : (n0 + bnn < N);

#define LOADG(k0, buf)                                                         \
    {                                                                          \
        const float* Ap = A + (size_t)(m0 + arow) * lda + (k0) + ak;           \
        unsigned ad = as_b + (unsigned)(buf) * STGB;                           \
        cp16(ad,      Ap,     true);                                           \
        cp16(ad + 16, Ap + 4, true);                                           \
        unsigned bd = bs_b + (unsigned)(buf) * STGB;                           \
        if (TRANSB) {                                                          \
            const float* Bq = Bp + (size_t)(n0 + arow) * ldb + (k0) + ak;      \
            cp16(bd,      Bq,     bval);                                       \
            cp16(bd + 16, Bq + 4, bval);                                       \
        } else {                                                               \
            const float* Bq = Bp + (size_t)((k0) + bkk) * ldb + n0 + bnn;      \
            cp16(bd,      Bq,     bval);                                       \
            cp16(bd + 16, Bq + 4, bval);                                       \
        }                                                                      \
    }

    // prologue: stage tiles 0 and 1 (nt >= 2 for all our shapes)
    LOADG(0, 0);
    cp_commit();
    LOADG(BK, 1);
    cp_commit();

    for (int t = 0; t < nt; t++) {
        cp_wait<1>();        // tiles <= t complete (in-order groups)
        __syncthreads();     // tile t visible; all warps done reading buf (t-1)%3

        const int nxt = t + 2;
        if (nxt < nt) LOADG(nxt * BK, nxt % 3);   // overwrites buf (t-1)%3: safe
        cp_commit();                               // uniform group accounting

        const unsigned* Ab = Asb + (t % 3) * STGW;
        const unsigned* Bb = Bsb + (t % 3) * STGW;
#pragma unroll
        for (int ks = 0; ks < 2; ks++) {
            const int k0 = ks * 8;
            unsigned af[4][4], bf[4][2];
#pragma unroll
            for (int mt = 0; mt < 4; mt++) {
                const int rb = wm + mt * 16 + qid;
                af[mt][0] = f2tf(Ab[(rb    ) * ASTR + k0 + cid]);
                af[mt][1] = f2tf(Ab[(rb + 8) * ASTR + k0 + cid]);
                af[mt][2] = f2tf(Ab[(rb    ) * ASTR + k0 + cid + 4]);
                af[mt][3] = f2tf(Ab[(rb + 8) * ASTR + k0 + cid + 4]);
            }
#pragma unroll
            for (int ntl = 0; ntl < 4; ntl++) {
                const int nb = wn + ntl * 8 + qid;
                if (TRANSB) {
                    bf[ntl][0] = f2tf(Bb[nb * BSTRT + k0 + cid]);
                    bf[ntl][1] = f2tf(Bb[nb * BSTRT + k0 + cid + 4]);
                } else {
                    bf[ntl][0] = f2tf(Bb[(k0 + cid    ) * BSTRN + nb]);
                    bf[ntl][1] = f2tf(Bb[(k0 + cid + 4) * BSTRN + nb]);
                }
            }
#pragma unroll
            for (int mt = 0; mt < 4; mt++)
#pragma unroll
                for (int ntl = 0; ntl < 4; ntl++)
                    mma_tf32(acc[mt][ntl], af[mt], bf[ntl]);
        }
    }

#pragma unroll
    for (int mt = 0; mt < 4; mt++) {
        const int r0 = m0 + wm + mt * 16 + qid;
#pragma unroll
        for (int ntl = 0; ntl < 4; ntl++) {
            const int c0 = n0 + wn + ntl * 8 + cid * 2;
            float* d = acc[mt][ntl];
#pragma unroll
            for (int half = 0; half < 2; half++) {
                const int r = r0 + half * 8;
#pragma unroll
                for (int e = 0; e < 2; e++) {
                    const int n = c0 + e;
                    if (n < N) {
                        float v = d[half * 2 + e] * alpha;
                        if (bias) v += bias[n];
                        if (RELU) v = fmaxf(v, 0.f);
                        C[(size_t)r * ldc + n] = v;
                    }
                }
            }
        }
    }
#undef LOADG
}

constexpr int TGEMM_SMEM = 3 * 2 * 128 * 20 * 4;   // 61440 bytes

// ---------------- row softmax, register-resident (rows of 512) ---------------
__global__ void softmax_rows(float* __restrict__ p, int rows)
{
    constexpr int N = 512;
    int row = blockIdx.x * blockDim.y + threadIdx.y;
    if (row >= rows) return;
    float* d = p + (size_t)row * N;
    int lane = threadIdx.x;

    float4 v[4];
#pragma unroll
    for (int c = 0; c < 4; c++)
        v[c] = *(const float4*)(d + lane * 4 + c * 128);

    float m = -INFINITY;
#pragma unroll
    for (int c = 0; c < 4; c++)
        m = fmaxf(m, fmaxf(fmaxf(v[c].x, v[c].y), fmaxf(v[c].z, v[c].w)));
#pragma unroll
    for (int o = 16; o > 0; o >>= 1) m = fmaxf(m, __shfl_xor_sync(0xffffffffu, m, o));

    float s = 0.f;
#pragma unroll
    for (int c = 0; c < 4; c++) {
        v[c].x = __expf(v[c].x - m); v[c].y = __expf(v[c].y - m);
        v[c].z = __expf(v[c].z - m); v[c].w = __expf(v[c].w - m);
        s += (v[c].x + v[c].y) + (v[c].z + v[c].w);
    }
#pragma unroll
    for (int o = 16; o > 0; o >>= 1) s += __shfl_xor_sync(0xffffffffu, s, o);

    float inv = 1.f / s;
#pragma unroll
    for (int c = 0; c < 4; c++) {
        v[c].x *= inv; v[c].y *= inv; v[c].z *= inv; v[c].w *= inv;
        *(float4*)(d + lane * 4 + c * 128) = v[c];
    }
}

// ---------------- fused heads: em = dec@crf_w^T + crf_b; seg log-softmax ----
// One warp per row; single read of dec serves both outputs.
__global__ __launch_bounds__(256)
void heads_kernel(const float* __restrict__ dec,
                  const float* __restrict__ crf_w, const float* __restrict__ crf_b,
                  const float* __restrict__ ent_w, const float* __restrict__ ent_b,
                  float* __restrict__ em, float* __restrict__ out)
{
    using namespace cfg;
    const int warp = threadIdx.x >> 5;
    const int lane = threadIdx.x & 31;
    const int row = blockIdx.x * 8 + warp;
    const float* d = dec + (size_t)row * E;

    float4 dv[4];
#pragma unroll
    for (int c = 0; c < 4; c++)
        dv[c] = *(const float4*)(d + lane * 4 + c * 128);

    float part[26];
#pragma unroll
    for (int o = 0; o < 24; o++) {
        const float* w = crf_w + (size_t)o * E;
        float a = 0.f;
#pragma unroll
        for (int c = 0; c < 4; c++) {
            float4 wv = *(const float4*)(w + lane * 4 + c * 128);
            a += dv[c].x * wv.x + dv[c].y * wv.y + dv[c].z * wv.z + dv[c].w * wv.w;
        }
        part[o] = a;
    }
#pragma unroll
    for (int o = 0; o < 2; o++) {
        const float* w = ent_w + (size_t)o * E;
        float a = 0.f;
#pragma unroll
        for (int c = 0; c < 4; c++) {
            float4 wv = *(const float4*)(w + lane * 4 + c * 128);
            a += dv[c].x * wv.x + dv[c].y * wv.y + dv[c].z * wv.z + dv[c].w * wv.w;
        }
        part[24 + o] = a;
    }

#pragma unroll
    for (int o = 0; o < 26; o++)
#pragma unroll
        for (int s = 16; s > 0; s >>= 1)
            part[o] += __shfl_xor_sync(0xffffffffu, part[o], s);

    if (lane == 0) {
        float* er = em + (size_t)row * T;
#pragma unroll
        for (int o = 0; o < 24; o++) er[o] = part[o] + crf_b[o];
        float z0 = part[24] + ent_b[0];
        float z1 = part[25] + ent_b[1];
        float m = fmaxf(z0, z1);
        float lse = m + __logf(__expf(z0 - m) + __expf(z1 - m));
        out[BS + (size_t)row * 2 + 0] = z0 - lse;
        out[BS + (size_t)row * 2 + 1] = z1 - lse;
    }
}

// ---------------- CRF: normalizer + numerator (warp0), viterbi (warp1) ------
__global__ __launch_bounds__(64)
void crf_kernel(const float* __restrict__ em, const int* __restrict__ labels,
                const unsigned char* __restrict__ mask,
                const float* __restrict__ start_t, const float* __restrict__ end_t,
                const float* __restrict__ trans,
                float* __restrict__ out,
                float* __restrict__ num, float* __restrict__ den,
                float* __restrict__ msum)
{
    using namespace cfg;
    const int b = blockIdx.x;
    const int warp = threadIdx.x >> 5;
    const int lane = threadIdx.x & 31;
    const int j = lane < T ? lane : T - 1;

    __shared__ unsigned char hist[S - 1][T];
    __shared__ unsigned char path[S];

    float tc[T];
#pragma unroll
    for (int i = 0; i < T; i++) tc[i] = trans[i * T + j];

    const float* emb = em + (size_t)b * S * T;

    if (warp == 0) {
        float et[T];
#pragma unroll
        for (int i = 0; i < T; i++) et[i] = __expf(tc[i]);

        float sc = start_t[j] + emb[j];
        float e_cur = emb[T + j];
        for (int s = 1; s < S; s++) {
            float e_next = (s + 1 < S) ? emb[(s + 1) * T + j] : 0.f;
            float mk = mask[b * S + s] ? 1.f : 0.f;

            float M = sc;
#pragma unroll
            for (int o = 16; o > 0; o >>= 1) M = fmaxf(M, __shfl_xor_sync(0xffffffffu, M, o));
            float p = __expf(sc - M);
            float s0 = 0.f, s1 = 0.f, s2 = 0.f, s3 = 0.f;
#pragma unroll
            for (int i = 0; i < T; i += 4) {
                s0 = fmaf(__shfl_sync(0xffffffffu, p, i    ), et[i    ], s0);
                s1 = fmaf(__shfl_sync(0xffffffffu, p, i + 1), et[i + 1], s1);
                s2 = fmaf(__shfl_sync(0xffffffffu, p, i + 2), et[i + 2], s2);
                s3 = fmaf(__shfl_sync(0xffffffffu, p, i + 3), et[i + 3], s3);
            }
            float inner = (s0 + s1) + (s2 + s3);
            float nxt = M + __logf(inner) + e_cur;
            sc = mk > 0.f ? nxt : sc;
            e_cur = e_next;
        }
        float x = (lane < T) ? sc + end_t[j] : -INFINITY;
        float m = x;
#pragma unroll
        for (int o = 16; o > 0; o >>= 1) m = fmaxf(m, __shfl_xor_sync(0xffffffffu, m, o));
        float sum = (lane < T) ? __expf(x - m) : 0.f;
#pragma unroll
        for (int o = 16; o > 0; o >>= 1) sum += __shfl_xor_sync(0xffffffffu, sum, o);
        float d = m + __logf(sum);

        float part = 0.f, ms = 0.f;
        for (int s = lane; s < S; s += 32) ms += mask[b * S + s] ? 1.f : 0.f;
        for (int s = 1 + lane; s < S; s += 32) {
            int lp = labels[b * S + s - 1];
            int lc = labels[b * S + s];
            float mf = mask[b * S + s] ? 1.f : 0.f;
            part += (trans[lp * T + lc] + emb[s * T + lc]) * mf;
        }
#pragma unroll
        for (int o = 16; o > 0; o >>= 1) {
            part += __shfl_xor_sync(0xffffffffu, part, o);
            ms   += __shfl_xor_sync(0xffffffffu, ms, o);
        }
        if (lane == 0) {
            int se = (int)ms - 1;
            int l0 = labels[b * S + 0];
            int lt = labels[b * S + se];
            num[b]  = start_t[l0] + emb[l0] + part + end_t[lt];
            den[b]  = d;
            msum[b] = ms;
        }
    } else {
        float sc = start_t[j] + emb[j];
        float e_cur = emb[T + j];
        for (int s = 1; s < S; s++) {
            float e_next = (s + 1 < S) ? emb[(s + 1) * T + j] : 0.f;

            float bv[12]; int bi[12];
#pragma unroll
            for (int i = 0; i < 12; i++) {
                float va = __shfl_sync(0xffffffffu, sc, 2 * i    ) + tc[2 * i    ];
                float vb = __shfl_sync(0xffffffffu, sc, 2 * i + 1) + tc[2 * i + 1];
                bool gt = vb > va;
                bv[i] = gt ? vb : va;
                bi[i] = gt ? 2 * i + 1 : 2 * i;
            }
#pragma unroll
            for (int i = 0; i < 6; i++) {
                bool gt = bv[2 * i + 1] > bv[2 * i];
                bv[i] = gt ? bv[2 * i + 1] : bv[2 * i];
                bi[i] = gt ? bi[2 * i + 1] : bi[2 * i];
            }
#pragma unroll
            for (int i = 0; i < 3; i++) {
                bool gt = bv[2 * i + 1] > bv[2 * i];
                bv[i] = gt ? bv[2 * i + 1] : bv[2 * i];
                bi[i] = gt ? bi[2 * i + 1] : bi[2 * i];
            }
            bool g1 = bv[1] > bv[0];
            float v01 = g1 ? bv[1] : bv[0];
            int   i01 = g1 ? bi[1] : bi[0];
            bool g2 = bv[2] > v01;
            float best = g2 ? bv[2] : v01;
            int   bix  = g2 ? bi[2] : i01;

            if (lane < T) hist[s - 1][j] = (unsigned char)bix;
            sc = best + e_cur;
            e_cur = e_next;
        }
        float x = (lane < T) ? sc + end_t[j] : -INFINITY;
        int idx = lane;
#pragma unroll
        for (int o = 16; o > 0; o >>= 1) {
            float ov = __shfl_down_sync(0xffffffffu, x, o);
            int   oi = __shfl_down_sync(0xffffffffu, idx, o);
            if (ov > x || (ov == x && oi < idx)) { x = ov; idx = oi; }
        }
        idx = __shfl_sync(0xffffffffu, idx, 0);
        __syncwarp();
        if (lane == 0) {
            int cur = idx;
            path[S - 1] = (unsigned char)cur;
            for (int s = S - 1; s >= 1; s--) {
                cur = hist[s - 1][cur];
                path[s - 1] = (unsigned char)cur;
            }
        }
        __syncwarp();
        for (int s = lane; s < S; s += 32)
            out[b * S + s] = (float)path[s];
    }
}

// ---------------- final scalar: -llh ----------------------------------------
__global__ void llh_kernel(const float* __restrict__ num, const float* __restrict__ den,
                           const float* __restrict__ msum, float* __restrict__ out)
{
    using namespace cfg;
    int lane = threadIdx.x;
    float v = (lane < B) ? num[lane] - den[lane] : 0.f;
    float m = (lane < B) ? msum[lane] : 0.f;
#pragma unroll
    for (int o = 16; o > 0; o >>= 1) {
        v += __shfl_xor_sync(0xffffffffu, v, o);
        m += __shfl_xor_sync(0xffffffffu, m, o);
    }
    if (lane == 0) out[3 * BS] = -(v / m);
}

// ---------------- host launch ------------------------------------------------
extern "C" void kernel_launch(void* const* d_in, const int* in_sizes, int n_in,
                              void* d_out, int out_size)
{
    using namespace cfg;
    const float* x       = (const float*)d_in[0];
    const int*   labels  = (const int*)d_in[1];
    const unsigned char* mask = (const unsigned char*)d_in[2];
    const float* Win     = (const float*)d_in[3];
    const float* bin     = (const float*)d_in[4];
    const float* Wout    = (const float*)d_in[5];
    const float* bout    = (const float*)d_in[6];
    const float* crf_w   = (const float*)d_in[7];
    const float* crf_b   = (const float*)d_in[8];
    const float* start_t = (const float*)d_in[9];
    const float* end_t   = (const float*)d_in[10];
    const float* trans   = (const float*)d_in[11];
    const float* ent_w   = (const float*)d_in[12];
    const float* ent_b   = (const float*)d_in[13];
    float* out = (float*)d_out;

    float *qkv, *scores, *attn, *dec, *em, *num, *den, *msum;
    cudaGetSymbolAddress((void**)&qkv,    g_qkv);
    cudaGetSymbolAddress((void**)&scores, g_scores);
    cudaGetSymbolAddress((void**)&attn,   g_attn);
    cudaGetSymbolAddress((void**)&dec,    g_dec);
    cudaGetSymbolAddress((void**)&em,     g_em);
    cudaGetSymbolAddress((void**)&num,    g_num);
    cudaGetSymbolAddress((void**)&den,    g_den);
    cudaGetSymbolAddress((void**)&msum,   g_msum);

    // opt-in dynamic smem (61440 B) for each tgemm instantiation
    cudaFuncSetAttribute(tgemm<true, false>,
                         cudaFuncAttributeMaxDynamicSharedMemorySize, TGEMM_SMEM);
    cudaFuncSetAttribute(tgemm<false, false>,
                         cudaFuncAttributeMaxDynamicSharedMemorySize, TGEMM_SMEM);
    cudaFuncSetAttribute(tgemm<true, true>,
                         cudaFuncAttributeMaxDynamicSharedMemorySize, TGEMM_SMEM);

    // 1) qkv = x @ Win^T + bin          (16384 x 1536 x 512)
    tgemm<true, false><<<dim3(12, 128, 1), 256, TGEMM_SMEM>>>(
        x, Win, qkv, bin, BS, 3 * E, E, E, E, 3 * E, 1.f,
        1, 0, 0, 0, 0, 0, 0);

    // 2) scores = Q K^T / 16            (batched 64: 512 x 512 x 256)
    tgemm<true, false><<<dim3(4, 4, 64), 256, TGEMM_SMEM>>>(
        qkv, qkv + E, scores, nullptr, S, S, HD, 3 * E, 3 * E, S, 1.f / 16.f,
        H, S * 3 * E, HD, S * 3 * E, HD, H * S * S, S * S);

    // 3) softmax over k
    softmax_rows<<<(B * H * S) / 8, dim3(32, 8)>>>(scores, B * H * S);

    // 4) attn = P @ V                   (batched 64: 512 x 256 x 512)
    tgemm<false, false><<<dim3(2, 4, 64), 256, TGEMM_SMEM>>>(
        scores, qkv + 2 * E, attn, nullptr, S, HD, S, S, 3 * E, E, 1.f,
        H, H * S * S, S * S, S * 3 * E, HD, S * E, HD);

    // 5) dec = relu(attn @ Wout^T + bout)
    tgemm<true, true><<<dim3(4, 128, 1), 256, TGEMM_SMEM>>>(
        attn, Wout, dec, bout, BS, E, E, E, E, E, 1.f,
        1, 0, 0, 0, 0, 0, 0);

    // 6) fused heads: em (fp32) + seg log-softmax, one dec read
    heads_kernel<<<BS / 8, 256>>>(dec, crf_w, crf_b, ent_w, ent_b, em, out);

    // 7) CRF
    crf_kernel<<<B, 64>>>(em, labels, mask, start_t, end_t, trans,
                          out, num, den, msum);

    // 8) scalar loss
    llh_kernel<<<1, 32>>>(num, den, msum, out);
}